// round 6
// baseline (speedup 1.0000x reference)
#include <cuda_runtime.h>

typedef unsigned long long ull;

// ---------------- packed f32x2 helpers (Blackwell) ----------------
__device__ __forceinline__ ull bc2(float f) {
    ull r; asm("mov.b64 %0, {%1, %1};" : "=l"(r) : "f"(f)); return r;
}
__device__ __forceinline__ ull pk2(float a, float b) {
    ull r; asm("mov.b64 %0, {%1, %2};" : "=l"(r) : "f"(a), "f"(b)); return r;
}
__device__ __forceinline__ float2 up2(ull u) {
    float2 v; asm("mov.b64 {%0, %1}, %2;" : "=f"(v.x), "=f"(v.y) : "l"(u)); return v;
}
__device__ __forceinline__ ull mul2(ull a, ull b) {
    ull r; asm("mul.rn.f32x2 %0, %1, %2;" : "=l"(r) : "l"(a), "l"(b)); return r;
}
__device__ __forceinline__ ull fma2(ull a, ull b, ull c) {
    ull r; asm("fma.rn.f32x2 %0, %1, %2, %3;" : "=l"(r) : "l"(a), "l"(b), "l"(c)); return r;
}

// q-index into a stage's [512][2][2] twiddle table for element pair (p, p+s).
__device__ __forceinline__ int qidx(int p, int ls) {
    int s = 1 << ls;
    return ((p >> (ls + 1)) << ls) | (p & (s - 1));
}

// Transpose-buffer padding: store side p=8t+e -> (p+(p>>4)) mod16 distinct
// across 16 lanes (2-cycle, optimal for 64-bit); read side p=t+128e conflict-free.
__device__ __forceinline__ int phys(int p) { return p + (p >> 4); }

static const int NGROUPS_TOTAL = 8192;   // 32768 rows / 4 per group (C=2 row-pairs)
static const int GRID = 296;             // 148 SMs x 2 CTAs

// ---------------- persistent main kernel ----------------
// Block = 128 threads; each iteration processes 4 rows (2 packed row-pairs).
// Twiddles: loaded ONCE per block into registers (inline repack), reused over
// ~28 iterations. C=2 keeps D at 32 regs so total ~225 regs -> NO spills
// (R5 lesson: C=4 demanded ~260 > 255 cap and spilled).
__global__ void __launch_bounds__(128, 2) butterfly_main(
    const float* __restrict__ x,
    const float* __restrict__ tw,       // [10][512][2][2]
    const float* __restrict__ bias,
    float* __restrict__ out)
{
    __shared__ float2 buf[2][1088];
    const int t = threadIdx.x;
    const float4* tw4 = reinterpret_cast<const float4*>(tw);  // [10][512] float4

    // ---- one-time twiddle load + repack into registers (160 floats) ----
    float tA[3][4][4];   // phase A: [ls][j][t00,t01,t10,t11]
    float tB[4][4][4];   // phase B: [ls-3][j][ta0,tb0,ta1,tb1]
    float tC[3][4][4];   // phase C: [ls-7][j][t00,t01,t10,t11]

    #pragma unroll
    for (int ls = 0; ls < 3; ls++) {
        const int s = 1 << ls;
        #pragma unroll
        for (int j = 0; j < 4; j++) {
            int eL = ((j >> ls) << (ls + 1)) | (j & (s - 1));
            float4 w = tw4[ls * 512 + qidx(8 * t + eL, ls)];
            tA[ls][j][0] = w.x; tA[ls][j][1] = w.y; tA[ls][j][2] = w.z; tA[ls][j][3] = w.w;
        }
    }
    #pragma unroll
    for (int ls = 3; ls < 7; ls++) {
        const int i = (t >> (ls - 3)) & 1;
        #pragma unroll
        for (int j = 0; j < 4; j++) {
            float4 w0 = tw4[ls * 512 + qidx(8 * t + 2 * j,     ls)];
            float4 w1 = tw4[ls * 512 + qidx(8 * t + 2 * j + 1, ls)];
            // role 0: out = t00*own + t01*other ; role 1: out = t11*own + t10*other
            tB[ls-3][j][0] = i ? w0.w : w0.x;
            tB[ls-3][j][1] = i ? w0.z : w0.y;
            tB[ls-3][j][2] = i ? w1.w : w1.x;
            tB[ls-3][j][3] = i ? w1.z : w1.y;
        }
    }
    #pragma unroll
    for (int ls = 7; ls < 10; ls++) {
        const int sig = 1 << (ls - 7);
        #pragma unroll
        for (int j = 0; j < 4; j++) {
            int eL = ((j >> (ls - 7)) << (ls - 7 + 1)) | (j & (sig - 1));
            float4 w = tw4[ls * 512 + qidx(t + 128 * eL, ls)];
            tC[ls-7][j][0] = w.x; tC[ls-7][j][1] = w.y; tC[ls-7][j][2] = w.z; tC[ls-7][j][3] = w.w;
        }
    }

    // bias for phase-C ownership p = t + 128e (same every iteration)
    float bv[8];
    #pragma unroll
    for (int e = 0; e < 8; e++) bv[e] = bias[t + 128 * e];

    // ---- persistent loop over 4-row groups ----
    for (int g = blockIdx.x; g < NGROUPS_TOTAL; g += GRID) {
        const int rowbase = g * 4;

        // input: direct register load (phase-A ownership p = 8t+e is 32 contiguous B)
        ull D[2][8];
        #pragma unroll
        for (int c = 0; c < 2; c++) {
            const float4* r0 = reinterpret_cast<const float4*>(x + (size_t)(rowbase + 2*c    ) * 1024 + 8 * t);
            const float4* r1 = reinterpret_cast<const float4*>(x + (size_t)(rowbase + 2*c + 1) * 1024 + 8 * t);
            float4 a0 = __ldcs(r0);     float4 a1 = __ldcs(r0 + 1);
            float4 b0 = __ldcs(r1);     float4 b1 = __ldcs(r1 + 1);
            D[c][0] = pk2(a0.x, b0.x);  D[c][1] = pk2(a0.y, b0.y);
            D[c][2] = pk2(a0.z, b0.z);  D[c][3] = pk2(a0.w, b0.w);
            D[c][4] = pk2(a1.x, b1.x);  D[c][5] = pk2(a1.y, b1.y);
            D[c][6] = pk2(a1.z, b1.z);  D[c][7] = pk2(a1.w, b1.w);
        }

        // phase A: strides 1,2,4 (intra-thread)
        #pragma unroll
        for (int ls = 0; ls < 3; ls++) {
            const int s = 1 << ls;
            #pragma unroll
            for (int j = 0; j < 4; j++) {
                const int eL = ((j >> ls) << (ls + 1)) | (j & (s - 1));
                const int eH = eL + s;
                ull t00 = bc2(tA[ls][j][0]), t01 = bc2(tA[ls][j][1]);
                ull t10 = bc2(tA[ls][j][2]), t11 = bc2(tA[ls][j][3]);
                #pragma unroll
                for (int c = 0; c < 2; c++) {
                    ull x0 = D[c][eL], x1 = D[c][eH];
                    D[c][eL] = fma2(t00, x0, mul2(t01, x1));
                    D[c][eH] = fma2(t10, x0, mul2(t11, x1));
                }
            }
        }

        // phase B: strides 8,16,32,64 via warp shuffles (lane xor 1,2,4,8)
        #pragma unroll
        for (int ls = 3; ls < 7; ls++) {
            const int k = 1 << (ls - 3);
            #pragma unroll
            for (int j = 0; j < 4; j++) {
                ull ta0 = bc2(tB[ls-3][j][0]), tb0 = bc2(tB[ls-3][j][1]);
                ull ta1 = bc2(tB[ls-3][j][2]), tb1 = bc2(tB[ls-3][j][3]);
                const int e0 = 2 * j, e1 = 2 * j + 1;
                #pragma unroll
                for (int c = 0; c < 2; c++) {
                    ull o0 = __shfl_xor_sync(0xffffffffu, D[c][e0], k);
                    D[c][e0] = fma2(ta0, D[c][e0], mul2(tb0, o0));
                    ull o1 = __shfl_xor_sync(0xffffffffu, D[c][e1], k);
                    D[c][e1] = fma2(ta1, D[c][e1], mul2(tb1, o1));
                }
            }
        }

        // ownership transpose through shared: p = 8t+e  ->  p = t+128e
        #pragma unroll
        for (int c = 0; c < 2; c++)
            #pragma unroll
            for (int e = 0; e < 8; e++) {
                int p = 8 * t + e;
                buf[c][phys(p)] = up2(D[c][e]);
            }
        __syncthreads();
        #pragma unroll
        for (int c = 0; c < 2; c++)
            #pragma unroll
            for (int e = 0; e < 8; e++) {
                int p = t + 128 * e;
                float2 v = buf[c][phys(p)];
                D[c][e] = pk2(v.x, v.y);
            }

        // phase C: strides 128,256,512 (intra-thread in e)
        #pragma unroll
        for (int ls = 7; ls < 10; ls++) {
            const int sig = 1 << (ls - 7);
            #pragma unroll
            for (int j = 0; j < 4; j++) {
                const int eL = ((j >> (ls - 7)) << (ls - 7 + 1)) | (j & (sig - 1));
                const int eH = eL + sig;
                ull t00 = bc2(tC[ls-7][j][0]), t01 = bc2(tC[ls-7][j][1]);
                ull t10 = bc2(tC[ls-7][j][2]), t11 = bc2(tC[ls-7][j][3]);
                #pragma unroll
                for (int c = 0; c < 2; c++) {
                    ull x0 = D[c][eL], x1 = D[c][eH];
                    D[c][eL] = fma2(t00, x0, mul2(t01, x1));
                    D[c][eH] = fma2(t10, x0, mul2(t11, x1));
                }
            }
        }

        // epilogue: bias + coalesced streaming stores
        #pragma unroll
        for (int c = 0; c < 2; c++) {
            float* o0 = out + (size_t)(rowbase + 2*c    ) * 1024;
            float* o1 = out + (size_t)(rowbase + 2*c + 1) * 1024;
            #pragma unroll
            for (int e = 0; e < 8; e++) {
                float2 v = up2(D[c][e]);
                int p = t + 128 * e;
                __stcs(o0 + p, v.x + bv[e]);
                __stcs(o1 + p, v.y + bv[e]);
            }
        }

        // protect buf before next iteration's transpose stores
        __syncthreads();
    }
}

extern "C" void kernel_launch(void* const* d_in, const int* in_sizes, int n_in,
                              void* d_out, int out_size) {
    const float* x    = (const float*)d_in[0];   // [32768, 1024]
    const float* tw   = (const float*)d_in[1];   // [1,1,10,512,2,2]
    const float* bias = (const float*)d_in[2];   // [1024]
    float* out = (float*)d_out;

    butterfly_main<<<GRID, 128>>>(x, tw, bias, out);
}

// round 7
// speedup vs baseline: 1.1905x; 1.1905x over previous
#include <cuda_runtime.h>

typedef unsigned long long ull;

// ---------------- packed f32x2 helpers (Blackwell) ----------------
__device__ __forceinline__ ull bc2(float f) {
    ull r; asm("mov.b64 %0, {%1, %1};" : "=l"(r) : "f"(f)); return r;
}
__device__ __forceinline__ ull pk2(float a, float b) {
    ull r; asm("mov.b64 %0, {%1, %2};" : "=l"(r) : "f"(a), "f"(b)); return r;
}
__device__ __forceinline__ float2 up2(ull u) {
    float2 v; asm("mov.b64 {%0, %1}, %2;" : "=f"(v.x), "=f"(v.y) : "l"(u)); return v;
}
__device__ __forceinline__ ull mul2(ull a, ull b) {
    ull r; asm("mul.rn.f32x2 %0, %1, %2;" : "=l"(r) : "l"(a), "l"(b)); return r;
}
__device__ __forceinline__ ull fma2(ull a, ull b, ull c) {
    ull r; asm("fma.rn.f32x2 %0, %1, %2, %3;" : "=l"(r) : "l"(a), "l"(b), "l"(c)); return r;
}

// cp.async 16B: global -> shared (L2-cached, bypasses L1 fill)
__device__ __forceinline__ void cpa16(void* dst_smem, const void* src) {
    unsigned sa = (unsigned)__cvta_generic_to_shared(dst_smem);
    asm volatile("cp.async.cg.shared.global [%0], [%1], 16;" :: "r"(sa), "l"(src));
}

// q-index into a stage's [512][2][2] twiddle table for element pair (p, p+s).
__device__ __forceinline__ int qidx(int p, int ls) {
    int s = 1 << ls;
    return ((p >> (ls + 1)) << ls) | (p & (s - 1));
}

// Transpose-buffer padding (1/32): store side p=8t+e -> phys mod 32 distinct
// within each 16-lane phase of a 64-bit access; read side p=t+128e also
// conflict-free. Verified by enumeration mod 32.
__device__ __forceinline__ int phys(int p) { return p + (p >> 5); }

static const int NGROUPS_TOTAL = 8192;   // 32768 rows / 4 per group (C=2 row-pairs)
static const int GRID = 296;             // 148 SMs x 2 CTAs

// ---------------- persistent main kernel ----------------
// Block = 128 threads; each iteration = 4 rows (2 packed row-pairs).
// Twiddles: register-cached once per block (as in R6).
// NEW (R7): double-buffered cp.async input staging -> DRAM latency of the
// next group's input is overlapped with the current group's compute.
// Each thread stages ONLY its own bytes (self-consumed, no barrier needed).
__global__ void __launch_bounds__(128, 2) butterfly_main(
    const float* __restrict__ x,
    const float* __restrict__ tw,       // [10][512][2][2]
    const float* __restrict__ bias,
    float* __restrict__ out)
{
    __shared__ float2 buf[1056];            // one row-pair transpose buffer (2-pass)
    __shared__ float4 xin[2 * 4 * 256];     // [buffer][row][f4] input staging, 32 KB
    const int t = threadIdx.x;
    const float4* tw4 = reinterpret_cast<const float4*>(tw);  // [10][512] float4

    // ---- one-time twiddle load + repack into registers (160 floats) ----
    float tA[3][4][4];   // phase A: [ls][j][t00,t01,t10,t11]
    float tB[4][4][4];   // phase B: [ls-3][j][ta0,tb0,ta1,tb1]
    float tC[3][4][4];   // phase C: [ls-7][j][t00,t01,t10,t11]

    #pragma unroll
    for (int ls = 0; ls < 3; ls++) {
        const int s = 1 << ls;
        #pragma unroll
        for (int j = 0; j < 4; j++) {
            int eL = ((j >> ls) << (ls + 1)) | (j & (s - 1));
            float4 w = tw4[ls * 512 + qidx(8 * t + eL, ls)];
            tA[ls][j][0] = w.x; tA[ls][j][1] = w.y; tA[ls][j][2] = w.z; tA[ls][j][3] = w.w;
        }
    }
    #pragma unroll
    for (int ls = 3; ls < 7; ls++) {
        const int i = (t >> (ls - 3)) & 1;
        #pragma unroll
        for (int j = 0; j < 4; j++) {
            float4 w0 = tw4[ls * 512 + qidx(8 * t + 2 * j,     ls)];
            float4 w1 = tw4[ls * 512 + qidx(8 * t + 2 * j + 1, ls)];
            // role 0: out = t00*own + t01*other ; role 1: out = t11*own + t10*other
            tB[ls-3][j][0] = i ? w0.w : w0.x;
            tB[ls-3][j][1] = i ? w0.z : w0.y;
            tB[ls-3][j][2] = i ? w1.w : w1.x;
            tB[ls-3][j][3] = i ? w1.z : w1.y;
        }
    }
    #pragma unroll
    for (int ls = 7; ls < 10; ls++) {
        const int sig = 1 << (ls - 7);
        #pragma unroll
        for (int j = 0; j < 4; j++) {
            int eL = ((j >> (ls - 7)) << (ls - 7 + 1)) | (j & (sig - 1));
            float4 w = tw4[ls * 512 + qidx(t + 128 * eL, ls)];
            tC[ls-7][j][0] = w.x; tC[ls-7][j][1] = w.y; tC[ls-7][j][2] = w.z; tC[ls-7][j][3] = w.w;
        }
    }

    // bias for phase-C ownership p = t + 128e (same every iteration)
    float bv[8];
    #pragma unroll
    for (int e = 0; e < 8; e++) bv[e] = bias[t + 128 * e];

    // ---- prologue: stage first group's input ----
    const int g0 = blockIdx.x;
    if (g0 < NGROUPS_TOTAL) {
        #pragma unroll
        for (int r = 0; r < 4; r++) {
            const float* src = x + (size_t)(g0 * 4 + r) * 1024 + 8 * t;
            float4* dst = &xin[(0 * 4 + r) * 256 + 2 * t];
            cpa16(dst, src);
            cpa16(dst + 1, src + 4);
        }
    }
    asm volatile("cp.async.commit_group;");

    int par = 0;
    // ---- persistent loop over 4-row groups ----
    for (int g = g0; g < NGROUPS_TOTAL; g += GRID) {
        // stage NEXT group's input into the other buffer (overlaps compute)
        const int gn = g + GRID;
        if (gn < NGROUPS_TOTAL) {
            #pragma unroll
            for (int r = 0; r < 4; r++) {
                const float* src = x + (size_t)(gn * 4 + r) * 1024 + 8 * t;
                float4* dst = &xin[((par ^ 1) * 4 + r) * 256 + 2 * t];
                cpa16(dst, src);
                cpa16(dst + 1, src + 4);
            }
        }
        asm volatile("cp.async.commit_group;");
        asm volatile("cp.async.wait_group 1;");   // current buffer landed

        // read this group's input from smem (self-staged -> no barrier)
        ull D[2][8];
        #pragma unroll
        for (int c = 0; c < 2; c++) {
            const float4* s0 = &xin[(par * 4 + 2 * c    ) * 256 + 2 * t];
            const float4* s1 = &xin[(par * 4 + 2 * c + 1) * 256 + 2 * t];
            float4 a0 = s0[0], a1 = s0[1];
            float4 b0 = s1[0], b1 = s1[1];
            D[c][0] = pk2(a0.x, b0.x);  D[c][1] = pk2(a0.y, b0.y);
            D[c][2] = pk2(a0.z, b0.z);  D[c][3] = pk2(a0.w, b0.w);
            D[c][4] = pk2(a1.x, b1.x);  D[c][5] = pk2(a1.y, b1.y);
            D[c][6] = pk2(a1.z, b1.z);  D[c][7] = pk2(a1.w, b1.w);
        }
        par ^= 1;

        // phase A: strides 1,2,4 (intra-thread)
        #pragma unroll
        for (int ls = 0; ls < 3; ls++) {
            const int s = 1 << ls;
            #pragma unroll
            for (int j = 0; j < 4; j++) {
                const int eL = ((j >> ls) << (ls + 1)) | (j & (s - 1));
                const int eH = eL + s;
                ull t00 = bc2(tA[ls][j][0]), t01 = bc2(tA[ls][j][1]);
                ull t10 = bc2(tA[ls][j][2]), t11 = bc2(tA[ls][j][3]);
                #pragma unroll
                for (int c = 0; c < 2; c++) {
                    ull x0 = D[c][eL], x1 = D[c][eH];
                    D[c][eL] = fma2(t00, x0, mul2(t01, x1));
                    D[c][eH] = fma2(t10, x0, mul2(t11, x1));
                }
            }
        }

        // phase B: strides 8,16,32,64 via warp shuffles (lane xor 1,2,4,8)
        #pragma unroll
        for (int ls = 3; ls < 7; ls++) {
            const int k = 1 << (ls - 3);
            #pragma unroll
            for (int j = 0; j < 4; j++) {
                ull ta0 = bc2(tB[ls-3][j][0]), tb0 = bc2(tB[ls-3][j][1]);
                ull ta1 = bc2(tB[ls-3][j][2]), tb1 = bc2(tB[ls-3][j][3]);
                const int e0 = 2 * j, e1 = 2 * j + 1;
                #pragma unroll
                for (int c = 0; c < 2; c++) {
                    ull o0 = __shfl_xor_sync(0xffffffffu, D[c][e0], k);
                    D[c][e0] = fma2(ta0, D[c][e0], mul2(tb0, o0));
                    ull o1 = __shfl_xor_sync(0xffffffffu, D[c][e1], k);
                    D[c][e1] = fma2(ta1, D[c][e1], mul2(tb1, o1));
                }
            }
        }

        // ---- per row-pair: transpose (2-pass, small buf) + phase C + store ----
        #pragma unroll
        for (int c = 0; c < 2; c++) {
            __syncthreads();   // protect buf from previous pass's readers
            #pragma unroll
            for (int e = 0; e < 8; e++) {
                int p = 8 * t + e;
                buf[phys(p)] = up2(D[c][e]);
            }
            __syncthreads();
            #pragma unroll
            for (int e = 0; e < 8; e++) {
                int p = t + 128 * e;
                float2 v = buf[phys(p)];
                D[c][e] = pk2(v.x, v.y);
            }

            // phase C: strides 128,256,512 (intra-thread in e)
            #pragma unroll
            for (int ls = 7; ls < 10; ls++) {
                const int sig = 1 << (ls - 7);
                #pragma unroll
                for (int j = 0; j < 4; j++) {
                    const int eL = ((j >> (ls - 7)) << (ls - 7 + 1)) | (j & (sig - 1));
                    const int eH = eL + sig;
                    ull t00 = bc2(tC[ls-7][j][0]), t01 = bc2(tC[ls-7][j][1]);
                    ull t10 = bc2(tC[ls-7][j][2]), t11 = bc2(tC[ls-7][j][3]);
                    ull x0 = D[c][eL], x1 = D[c][eH];
                    D[c][eL] = fma2(t00, x0, mul2(t01, x1));
                    D[c][eH] = fma2(t10, x0, mul2(t11, x1));
                }
            }

            // epilogue: bias + coalesced streaming stores
            float* o0 = out + (size_t)(g * 4 + 2 * c    ) * 1024;
            float* o1 = out + (size_t)(g * 4 + 2 * c + 1) * 1024;
            #pragma unroll
            for (int e = 0; e < 8; e++) {
                float2 v = up2(D[c][e]);
                int p = t + 128 * e;
                __stcs(o0 + p, v.x + bv[e]);
                __stcs(o1 + p, v.y + bv[e]);
            }
        }
    }
}

extern "C" void kernel_launch(void* const* d_in, const int* in_sizes, int n_in,
                              void* d_out, int out_size) {
    const float* x    = (const float*)d_in[0];   // [32768, 1024]
    const float* tw   = (const float*)d_in[1];   // [1,1,10,512,2,2]
    const float* bias = (const float*)d_in[2];   // [1024]
    float* out = (float*)d_out;

    butterfly_main<<<GRID, 128>>>(x, tw, bias, out);
}